// round 1
// baseline (speedup 1.0000x reference)
#include <cuda_runtime.h>
#include <math.h>
#include <float.h>

// Problem constants (fixed by the reference)
#define B_      8
#define HQ_     32
#define HK_     8
#define D_      64
#define S_      32
#define NB_     128
#define T_      (NB_ * S_)
#define W_      1024
#define G_      (HQ_ / HK_)     // 4 q heads per kv head

#define NSPLIT  8               // split-KV factor
#define NWARPS  8
#define NTHREADS (NWARPS * 32)

// Scratch for split-KV partials (no cudaMalloc allowed)
// layout: idx = ((b*HK + hk)*G + g)*NSPLIT + split   == (b*32 + hq)*NSPLIT + split
__device__ float g_ml[B_ * HQ_ * NSPLIT * 2];     // (m, l) pairs
__device__ float g_acc[B_ * HQ_ * NSPLIT * D_];   // unnormalized acc

__global__ __launch_bounds__(NTHREADS)
void attn_partial_kernel(const float* __restrict__ q_last,
                         const float* __restrict__ k_last,
                         const float* __restrict__ v_last,
                         const float* __restrict__ cache,
                         const int*   __restrict__ block_ids,
                         const int*   __restrict__ start_pos)
{
    const int b     = blockIdx.x;
    const int hk    = blockIdx.y;
    const int split = blockIdx.z;
    const int tid   = threadIdx.x;
    const int w     = tid >> 5;
    const int lane  = tid & 31;

    const int pos = start_pos[b];
    const int t0  = max(0, pos - W_ + 1);
    const int L   = pos - t0 + 1;
    const int chunk = (L + NSPLIT - 1) / NSPLIT;
    const int ts = t0 + split * chunk;
    const int te = min(ts + chunk, pos + 1);

    // q for the G grouped heads: lane holds dims [2*lane, 2*lane+1]
    float2 qv[G_];
#pragma unroll
    for (int g = 0; g < G_; g++)
        qv[g] = ((const float2*)(q_last + ((size_t)b * HQ_ + hk * G_ + g) * D_))[lane];

    const float2* klast2 = (const float2*)(k_last + ((size_t)b * HK_ + hk) * D_);
    const float2* vlast2 = (const float2*)(v_last + ((size_t)b * HK_ + hk) * D_);

    float  m[G_], l[G_];
    float2 acc[G_];
#pragma unroll
    for (int g = 0; g < G_; g++) {
        m[g] = -INFINITY; l[g] = 0.f; acc[g] = make_float2(0.f, 0.f);
    }

    // each warp strides over positions in this split's range
    for (int t = ts + w; t < te; t += NWARPS) {
        const int page = block_ids[b * NB_ + (t >> 5)];   // S_ == 32
        const int off  = t & 31;
        const float2* kp;
        const float2* vp;
        if (t == pos) {
            kp = klast2; vp = vlast2;
        } else {
            const size_t kbase = ((((size_t)page * 2 + 0) * HK_ + hk) * S_ + off) * D_;
            kp = (const float2*)(cache + kbase);
            vp = (const float2*)(cache + kbase + (size_t)HK_ * S_ * D_);  // c=1 plane
        }
        const float2 kk = kp[lane];
        const float2 vv = vp[lane];

        float s[G_];
#pragma unroll
        for (int g = 0; g < G_; g++)
            s[g] = kk.x * qv[g].x + kk.y * qv[g].y;
#pragma unroll
        for (int o = 16; o >= 1; o >>= 1) {
#pragma unroll
            for (int g = 0; g < G_; g++)
                s[g] += __shfl_xor_sync(0xffffffffu, s[g], o);
        }
#pragma unroll
        for (int g = 0; g < G_; g++) {
            const float sc   = s[g] * 0.125f;           // 1/sqrt(64)
            const float mn   = fmaxf(m[g], sc);
            const float corr = __expf(m[g] - mn);       // exp(-inf - finite) = 0, safe
            const float p    = __expf(sc - mn);
            l[g] = l[g] * corr + p;
            acc[g].x = acc[g].x * corr + p * vv.x;
            acc[g].y = acc[g].y * corr + p * vv.y;
            m[g] = mn;
        }
    }

    // cross-warp combine
    __shared__ float sm[NWARPS][G_];
    __shared__ float sl[NWARPS][G_];
    __shared__ float sa[NWARPS][G_][D_];
#pragma unroll
    for (int g = 0; g < G_; g++) {
        if (lane == 0) { sm[w][g] = m[g]; sl[w][g] = l[g]; }
        sa[w][g][lane * 2]     = acc[g].x;
        sa[w][g][lane * 2 + 1] = acc[g].y;
    }
    __syncthreads();

    // 256 threads: (g, d)
    const int g = tid >> 6;
    const int d = tid & 63;

    float M = -INFINITY;
#pragma unroll
    for (int ww = 0; ww < NWARPS; ww++) M = fmaxf(M, sm[ww][g]);

    float Lt = 0.f, A = 0.f;
    if (M != -INFINITY) {
#pragma unroll
        for (int ww = 0; ww < NWARPS; ww++) {
            const float mw = sm[ww][g];
            const float c  = (mw == -INFINITY) ? 0.f : __expf(mw - M);
            Lt += sl[ww][g] * c;
            A  += sa[ww][g][d] * c;
        }
    }

    const int idx = ((b * HK_ + hk) * G_ + g) * NSPLIT + split;
    if (d == 0) { g_ml[idx * 2] = M; g_ml[idx * 2 + 1] = Lt; }
    g_acc[idx * D_ + d] = A;
}

__global__ __launch_bounds__(D_)
void attn_reduce_kernel(const float* __restrict__ sink,
                        float* __restrict__ out)
{
    const int bh = blockIdx.x;          // b*32 + hq
    const int d  = threadIdx.x;
    const int hq = bh & 31;
    const int base = bh * NSPLIT;

    const float snk = sink[hq];
    float M = snk;
#pragma unroll
    for (int s = 0; s < NSPLIT; s++) M = fmaxf(M, g_ml[(base + s) * 2]);

    float Lt = __expf(snk - M);
    float A  = 0.f;
#pragma unroll
    for (int s = 0; s < NSPLIT; s++) {
        const float ms = g_ml[(base + s) * 2];
        const float c  = (ms == -INFINITY) ? 0.f : __expf(ms - M);
        Lt += g_ml[(base + s) * 2 + 1] * c;
        A  += g_acc[(base + s) * D_ + d] * c;
    }
    out[(size_t)bh * D_ + d] = A / Lt;   // sink mass only in denominator
}

extern "C" void kernel_launch(void* const* d_in, const int* in_sizes, int n_in,
                              void* d_out, int out_size)
{
    const float* q_last     = (const float*)d_in[0];
    const float* k_last     = (const float*)d_in[1];
    const float* v_last     = (const float*)d_in[2];
    const float* cache      = (const float*)d_in[3];
    const int*   block_ids  = (const int*)d_in[4];
    const int*   start_pos  = (const int*)d_in[5];
    const float* sink       = (const float*)d_in[6];
    float*       out        = (float*)d_out;

    dim3 grid(B_, HK_, NSPLIT);
    attn_partial_kernel<<<grid, NTHREADS>>>(q_last, k_last, v_last, cache,
                                            block_ids, start_pos);
    attn_reduce_kernel<<<B_ * HQ_, D_>>>(sink, out);
}

// round 2
// speedup vs baseline: 1.2154x; 1.2154x over previous
#include <cuda_runtime.h>
#include <math.h>
#include <float.h>

// Problem constants (fixed by the reference)
#define B_      8
#define HQ_     32
#define HK_     8
#define D_      64
#define S_      32
#define NB_     128
#define T_      (NB_ * S_)
#define W_      1024
#define G_      (HQ_ / HK_)     // 4 q heads per kv head

#define NSPLIT  16              // split-KV factor
#define NWARPS  4
#define NTHREADS (NWARPS * 32)

// Scratch for split-KV partials (no cudaMalloc allowed)
// idx = ((b*HK + hk)*G + g)*NSPLIT + split
__device__ float g_ml[B_ * HQ_ * NSPLIT * 2];     // (m, l) pairs
__device__ float g_acc[B_ * HQ_ * NSPLIT * D_];   // unnormalized acc
__device__ int   g_cnt[B_ * HK_];                 // zero-init; self-resetting

__device__ __forceinline__ void load_kv(float4& kk, float4& vv,
                                        int t, bool valid,
                                        const float* __restrict__ cache,
                                        const int*   __restrict__ bid_row,
                                        int pos,
                                        const float4* __restrict__ klast4,
                                        const float4* __restrict__ vlast4,
                                        int hk, int laneh)
{
    if (!valid) { kk = make_float4(0.f,0.f,0.f,0.f); vv = kk; return; }
    if (t == pos) { kk = klast4[laneh]; vv = vlast4[laneh]; return; }
    const int page = bid_row[t >> 5];                 // S_ == 32
    const size_t kbase = ((((size_t)page * 2) * HK_ + hk) * S_ + (t & 31)) * (size_t)D_;
    kk = *(const float4*)(cache + kbase + laneh * 4);
    vv = *(const float4*)(cache + kbase + (size_t)HK_ * S_ * D_ + laneh * 4);
}

__global__ __launch_bounds__(NTHREADS)
void attn_fused_kernel(const float* __restrict__ q_last,
                       const float* __restrict__ k_last,
                       const float* __restrict__ v_last,
                       const float* __restrict__ cache,
                       const int*   __restrict__ block_ids,
                       const int*   __restrict__ start_pos,
                       const float* __restrict__ sink,
                       float*       __restrict__ out)
{
    const int b     = blockIdx.x;
    const int hk    = blockIdx.y;
    const int split = blockIdx.z;
    const int tid   = threadIdx.x;
    const int w     = tid >> 5;
    const int lane  = tid & 31;
    const int h     = lane >> 4;       // half-warp id: position parity
    const int laneh = lane & 15;       // 16 lanes cover D=64 as float4

    const int pos = start_pos[b];
    const int t0  = max(0, pos - W_ + 1);
    const int L   = pos - t0 + 1;
    const int chunk = (L + NSPLIT - 1) / NSPLIT;
    const int ts = t0 + split * chunk;
    const int te = min(ts + chunk, pos + 1);

    const int* bid_row = block_ids + b * NB_;
    const float4* klast4 = (const float4*)(k_last + ((size_t)b * HK_ + hk) * D_);
    const float4* vlast4 = (const float4*)(v_last + ((size_t)b * HK_ + hk) * D_);

    // q for the G grouped heads: lane holds dims [4*laneh .. 4*laneh+3]
    float4 qv[G_];
#pragma unroll
    for (int g = 0; g < G_; g++)
        qv[g] = ((const float4*)(q_last + ((size_t)b * HQ_ + hk * G_ + g) * D_))[laneh];

    float  m[G_], l[G_];
    float4 acc[G_];
#pragma unroll
    for (int g = 0; g < G_; g++) {
        m[g] = -INFINITY; l[g] = 0.f; acc[g] = make_float4(0.f,0.f,0.f,0.f);
    }

    const int stride = NWARPS * 2;
    int tp = ts + (w << 1);            // this warp's pair base
    int t  = tp + h;                   // this half's position
    bool valid = (t < te) && (tp < te);

    float4 kk, vv;
    load_kv(kk, vv, t, valid, cache, bid_row, pos, klast4, vlast4, hk, laneh);

    while (tp < te) {
        const int tpn = tp + stride;
        const int tn  = t + stride;
        const bool validn = (tn < te) && (tpn < te);
        float4 kkn = make_float4(0.f,0.f,0.f,0.f), vvn = kkn;
        if (tpn < te)
            load_kv(kkn, vvn, tn, validn, cache, bid_row, pos, klast4, vlast4, hk, laneh);

        float s[G_];
#pragma unroll
        for (int g = 0; g < G_; g++)
            s[g] = qv[g].x*kk.x + qv[g].y*kk.y + qv[g].z*kk.z + qv[g].w*kk.w;
#pragma unroll
        for (int o = 8; o >= 1; o >>= 1) {
#pragma unroll
            for (int g = 0; g < G_; g++)
                s[g] += __shfl_xor_sync(0xffffffffu, s[g], o);
        }
        if (valid) {
#pragma unroll
            for (int g = 0; g < G_; g++) {
                const float sc = s[g] * 0.125f;          // 1/sqrt(64)
                if (sc > m[g]) {                         // warp-half-uniform branch
                    const float corr = __expf(m[g] - sc); // exp(-inf)=0 on first hit
                    m[g] = sc;
                    l[g] *= corr;
                    acc[g].x *= corr; acc[g].y *= corr;
                    acc[g].z *= corr; acc[g].w *= corr;
                }
                const float p = __expf(sc - m[g]);
                l[g] += p;
                acc[g].x += p * vv.x; acc[g].y += p * vv.y;
                acc[g].z += p * vv.z; acc[g].w += p * vv.w;
            }
        }
        kk = kkn; vv = vvn; valid = validn; t = tn; tp = tpn;
    }

    // ---- merge the two half-warps (positions interleaved) ----
#pragma unroll
    for (int g = 0; g < G_; g++) {
        const float mo = __shfl_xor_sync(0xffffffffu, m[g], 16);
        const float lo = __shfl_xor_sync(0xffffffffu, l[g], 16);
        float4 ao;
        ao.x = __shfl_xor_sync(0xffffffffu, acc[g].x, 16);
        ao.y = __shfl_xor_sync(0xffffffffu, acc[g].y, 16);
        ao.z = __shfl_xor_sync(0xffffffffu, acc[g].z, 16);
        ao.w = __shfl_xor_sync(0xffffffffu, acc[g].w, 16);
        const float M  = fmaxf(m[g], mo);
        const float c0 = (m[g] == -INFINITY) ? 0.f : __expf(m[g] - M);
        const float c1 = (mo   == -INFINITY) ? 0.f : __expf(mo   - M);
        l[g] = l[g] * c0 + lo * c1;
        acc[g].x = acc[g].x * c0 + ao.x * c1;
        acc[g].y = acc[g].y * c0 + ao.y * c1;
        acc[g].z = acc[g].z * c0 + ao.z * c1;
        acc[g].w = acc[g].w * c0 + ao.w * c1;
        m[g] = M;
    }

    // ---- cross-warp combine via smem ----
    __shared__ float  sm_[NWARPS][G_];
    __shared__ float  sl_[NWARPS][G_];
    __shared__ float4 sa_[NWARPS][G_][16];
    if (lane < 16) {
#pragma unroll
        for (int g = 0; g < G_; g++) sa_[w][g][laneh] = acc[g];
    }
    if (lane == 0) {
#pragma unroll
        for (int g = 0; g < G_; g++) { sm_[w][g] = m[g]; sl_[w][g] = l[g]; }
    }
    __syncthreads();

#pragma unroll
    for (int rep = 0; rep < 2; rep++) {
        const int i = tid + rep * NTHREADS;        // 0..255
        const int g = i >> 6;
        const int d = i & 63;
        float M = -INFINITY;
#pragma unroll
        for (int ww = 0; ww < NWARPS; ww++) M = fmaxf(M, sm_[ww][g]);
        float Lt = 0.f, A = 0.f;
        if (M != -INFINITY) {
#pragma unroll
            for (int ww = 0; ww < NWARPS; ww++) {
                const float mw = sm_[ww][g];
                const float c  = (mw == -INFINITY) ? 0.f : __expf(mw - M);
                Lt += sl_[ww][g] * c;
                A  += ((const float*)&sa_[ww][g][0])[d] * c;
            }
        }
        const int idx = ((b * HK_ + hk) * G_ + g) * NSPLIT + split;
        if (d == 0) { g_ml[idx * 2] = M; g_ml[idx * 2 + 1] = Lt; }
        g_acc[idx * D_ + d] = A;
    }

    // ---- split-KV finalization: last CTA per (b,hk) reduces ----
    __shared__ int is_last;
    __threadfence();
    __syncthreads();
    if (tid == 0) {
        const int old = atomicAdd(&g_cnt[b * HK_ + hk], 1);
        is_last = (old == NSPLIT - 1);
    }
    __syncthreads();
    if (!is_last) return;
    __threadfence();

#pragma unroll
    for (int rep = 0; rep < 2; rep++) {
        const int i = tid + rep * NTHREADS;
        const int g = i >> 6;
        const int d = i & 63;
        const int hq = hk * G_ + g;
        const int base = ((b * HK_ + hk) * G_ + g) * NSPLIT;

        const float snk = sink[hq];
        float M = snk;
#pragma unroll
        for (int s = 0; s < NSPLIT; s++) M = fmaxf(M, g_ml[(base + s) * 2]);
        float Lt = __expf(snk - M);
        float A  = 0.f;
#pragma unroll
        for (int s = 0; s < NSPLIT; s++) {
            const float ms = g_ml[(base + s) * 2];
            const float c  = (ms == -INFINITY) ? 0.f : __expf(ms - M);
            Lt += g_ml[(base + s) * 2 + 1] * c;
            A  += g_acc[(base + s) * D_ + d] * c;
        }
        out[((size_t)b * HQ_ + hq) * D_ + d] = A / Lt;   // sink only in denominator
    }
    if (tid == 0) g_cnt[b * HK_ + hk] = 0;               // reset for next graph replay
}

extern "C" void kernel_launch(void* const* d_in, const int* in_sizes, int n_in,
                              void* d_out, int out_size)
{
    const float* q_last     = (const float*)d_in[0];
    const float* k_last     = (const float*)d_in[1];
    const float* v_last     = (const float*)d_in[2];
    const float* cache      = (const float*)d_in[3];
    const int*   block_ids  = (const int*)d_in[4];
    const int*   start_pos  = (const int*)d_in[5];
    const float* sink       = (const float*)d_in[6];
    float*       out        = (float*)d_out;

    dim3 grid(B_, HK_, NSPLIT);
    attn_fused_kernel<<<grid, NTHREADS>>>(q_last, k_last, v_last, cache,
                                          block_ids, start_pos, sink, out);
}

// round 4
// speedup vs baseline: 1.7843x; 1.4681x over previous
#include <cuda_runtime.h>
#include <math.h>

// Problem constants (fixed by the reference)
#define B_      8
#define HQ_     32
#define HK_     8
#define D_      64
#define S_      32
#define NB_     128
#define W_      1024
#define G_      (HQ_ / HK_)     // 4 q heads per kv head

#define NSPLIT  8
#define NWARPS  4
#define NTHREADS (NWARPS * 32)

// float4-unit strides in the cache [P, 2, Hk, S, D]:
//   page plane  = 2*HK*S*D/4 = 8192
//   hk offset   = S*D/4      = 512
//   V plane     = HK*S*D/4   = 4096
//   row offset  = D/4        = 16 per position-in-page
#define PG4   8192
#define HK4   512
#define VP4   4096

// Split-KV scratch (no cudaMalloc allowed)
// idx = ((b*HK + hk)*G + g)*NSPLIT + split
__device__ float g_l[B_ * HQ_ * NSPLIT];          // denominators (no max needed)
__device__ float g_acc[B_ * HQ_ * NSPLIT * D_];   // unnormalized acc
__device__ int   g_cnt[B_ * HK_];                 // zero-init; self-resetting

__device__ __forceinline__ float dot8(float4 qa, float4 qb, float4 ka, float4 kb)
{
    return qa.x*ka.x + qa.y*ka.y + qa.z*ka.z + qa.w*ka.w
         + qb.x*kb.x + qb.y*kb.y + qb.z*kb.z + qb.w*kb.w;
}

__global__ __launch_bounds__(NTHREADS)
void attn_fused_kernel(const float* __restrict__ q_last,
                       const float* __restrict__ k_last,
                       const float* __restrict__ v_last,
                       const float* __restrict__ cache,
                       const int*   __restrict__ block_ids,
                       const int*   __restrict__ start_pos,
                       const float* __restrict__ sink,
                       float*       __restrict__ out)
{
    const int b     = blockIdx.x;
    const int hk    = blockIdx.y;
    const int split = blockIdx.z;
    const int tid   = threadIdx.x;
    const int w     = tid >> 5;
    const int lane  = tid & 31;
    const int e     = lane & 7;        // 8 lanes cover a D=64 row (2x float4 each)

    const int pos = start_pos[b];
    const int t0  = max(0, pos - W_ + 1);
    const int L   = pos - t0 + 1;
    const int chunk = (L + NSPLIT - 1) / NSPLIT;
    const int ts  = t0 + split * chunk;
    const int te  = min(ts + chunk, pos + 1);
    const int te2 = min(te, pos);      // main loop excludes t == pos

    const float4* cache4 = (const float4*)cache;
    const int*    bid    = block_ids + b * NB_;

    // q, pre-scaled by 1/sqrt(64): lane e holds float4 slices e and e+8
    float4 qa[G_], qb[G_];
#pragma unroll
    for (int g = 0; g < G_; g++) {
        const float4* qr = (const float4*)(q_last + ((size_t)(b * HQ_ + hk * G_ + g)) * D_);
        float4 a = qr[e], bb = qr[e + 8];
        qa[g] = make_float4(a.x*0.125f,  a.y*0.125f,  a.z*0.125f,  a.w*0.125f);
        qb[g] = make_float4(bb.x*0.125f, bb.y*0.125f, bb.z*0.125f, bb.w*0.125f);
    }

    float  l[G_];
    float4 acca[G_], accb[G_];
#pragma unroll
    for (int g = 0; g < G_; g++) {
        l[g] = 0.f;
        acca[g] = make_float4(0.f,0.f,0.f,0.f);
        accb[g] = make_float4(0.f,0.f,0.f,0.f);
    }

    const int khk = hk * HK4;

    // ---- main loop: 4 positions per warp-iteration (lane groups of 8) ----
    {
        const int q4 = lane >> 3;                  // position within the warp's quad
        int wb = ts + (w << 2);
        if (wb < te2) {
            bool v = (wb + q4) < te2;
            int tc = v ? (wb + q4) : (te2 - 1);
            int idx = bid[tc >> 5] * PG4 + khk + (tc & 31) * 16 + e;
            float4 ka = cache4[idx],       kb = cache4[idx + 8];
            float4 va = cache4[idx + VP4], vb = cache4[idx + VP4 + 8];

            for (;;) {
                const int wn = wb + NWARPS * 4;
                float4 kan, kbn, van, vbn;
                bool vn = false;
                if (wn < te2) {
                    vn = (wn + q4) < te2;
                    const int tn = vn ? (wn + q4) : (te2 - 1);
                    const int in_ = bid[tn >> 5] * PG4 + khk + (tn & 31) * 16 + e;
                    kan = cache4[in_];       kbn = cache4[in_ + 8];
                    van = cache4[in_ + VP4]; vbn = cache4[in_ + VP4 + 8];
                }

                float s[G_];
#pragma unroll
                for (int g = 0; g < G_; g++) s[g] = dot8(qa[g], qb[g], ka, kb);
#pragma unroll
                for (int off = 4; off >= 1; off >>= 1) {
#pragma unroll
                    for (int g = 0; g < G_; g++)
                        s[g] += __shfl_xor_sync(0xffffffffu, s[g], off);
                }
#pragma unroll
                for (int g = 0; g < G_; g++) {
                    const float p = v ? __expf(s[g]) : 0.f;
                    l[g] += p;
                    acca[g].x += p * va.x; acca[g].y += p * va.y;
                    acca[g].z += p * va.z; acca[g].w += p * va.w;
                    accb[g].x += p * vb.x; accb[g].y += p * vb.y;
                    accb[g].z += p * vb.z; accb[g].w += p * vb.w;
                }

                if (wn >= te2) break;
                ka = kan; kb = kbn; va = van; vb = vbn; v = vn; wb = wn;
            }
        }
    }

    // ---- t == pos handled once, by warp 0 / lane-group 0 of the owning split ----
    if (pos >= ts && pos < te && w == 0 && lane < 8) {
        const float4* kr = (const float4*)(k_last + ((size_t)(b * HK_ + hk)) * D_);
        const float4* vr = (const float4*)(v_last + ((size_t)(b * HK_ + hk)) * D_);
        const float4 ka = kr[e], kb = kr[e + 8];
        const float4 va = vr[e], vb = vr[e + 8];
        float s[G_];
#pragma unroll
        for (int g = 0; g < G_; g++) s[g] = dot8(qa[g], qb[g], ka, kb);
#pragma unroll
        for (int off = 4; off >= 1; off >>= 1) {
#pragma unroll
            for (int g = 0; g < G_; g++)
                s[g] += __shfl_xor_sync(0x000000ffu, s[g], off);
        }
#pragma unroll
        for (int g = 0; g < G_; g++) {
            const float p = __expf(s[g]);
            l[g] += p;
            acca[g].x += p * va.x; acca[g].y += p * va.y;
            acca[g].z += p * va.z; acca[g].w += p * va.w;
            accb[g].x += p * vb.x; accb[g].y += p * vb.y;
            accb[g].z += p * vb.z; accb[g].w += p * vb.w;
        }
    }

    // ---- merge the 4 lane-groups of each warp (pure sums, no max) ----
#pragma unroll
    for (int g = 0; g < G_; g++) {
#pragma unroll
        for (int off = 8; off <= 16; off <<= 1) {
            l[g]      += __shfl_xor_sync(0xffffffffu, l[g], off);
            acca[g].x += __shfl_xor_sync(0xffffffffu, acca[g].x, off);
            acca[g].y += __shfl_xor_sync(0xffffffffu, acca[g].y, off);
            acca[g].z += __shfl_xor_sync(0xffffffffu, acca[g].z, off);
            acca[g].w += __shfl_xor_sync(0xffffffffu, acca[g].w, off);
            accb[g].x += __shfl_xor_sync(0xffffffffu, accb[g].x, off);
            accb[g].y += __shfl_xor_sync(0xffffffffu, accb[g].y, off);
            accb[g].z += __shfl_xor_sync(0xffffffffu, accb[g].z, off);
            accb[g].w += __shfl_xor_sync(0xffffffffu, accb[g].w, off);
        }
    }

    // ---- cross-warp combine via smem ----
    __shared__ float sl_[NWARPS][G_];
    __shared__ float sa_[NWARPS][G_][D_];
    if (lane < 8) {
#pragma unroll
        for (int g = 0; g < G_; g++) {
            ((float4*)sa_[w][g])[e]     = acca[g];
            ((float4*)sa_[w][g])[e + 8] = accb[g];
        }
    }
    if (lane == 0) {
#pragma unroll
        for (int g = 0; g < G_; g++) sl_[w][g] = l[g];
    }
    __syncthreads();

#pragma unroll
    for (int rep = 0; rep < 2; rep++) {
        const int i = tid + rep * NTHREADS;        // 0..255 -> (g,d)
        const int g = i >> 6;
        const int d = i & 63;
        float Lt = 0.f, A = 0.f;
#pragma unroll
        for (int ww = 0; ww < NWARPS; ww++) {
            Lt += sl_[ww][g];
            A  += sa_[ww][g][d];
        }
        const int idx = ((b * HK_ + hk) * G_ + g) * NSPLIT + split;
        if (d == 0) g_l[idx] = Lt;
        g_acc[idx * D_ + d] = A;
    }

    // ---- split-KV finalization: last CTA per (b,hk) reduces ----
    __shared__ int is_last;
    __threadfence();
    __syncthreads();
    if (tid == 0) {
        const int old = atomicAdd(&g_cnt[b * HK_ + hk], 1);
        is_last = (old == NSPLIT - 1);
    }
    __syncthreads();
    if (!is_last) return;
    __threadfence();

#pragma unroll
    for (int rep = 0; rep < 2; rep++) {
        const int i = tid + rep * NTHREADS;
        const int g = i >> 6;
        const int d = i & 63;
        const int hq = hk * G_ + g;
        const int base = ((b * HK_ + hk) * G_ + g) * NSPLIT;

        float Lt = __expf(sink[hq]);               // sink mass, denominator only
        float A  = 0.f;
#pragma unroll
        for (int s = 0; s < NSPLIT; s++) {
            Lt += g_l[base + s];
            A  += g_acc[(base + s) * D_ + d];
        }
        out[((size_t)(b * HQ_ + hq)) * D_ + d] = A / Lt;
    }
    if (tid == 0) g_cnt[b * HK_ + hk] = 0;         // reset for next graph replay
}

extern "C" void kernel_launch(void* const* d_in, const int* in_sizes, int n_in,
                              void* d_out, int out_size)
{
    const float* q_last     = (const float*)d_in[0];
    const float* k_last     = (const float*)d_in[1];
    const float* v_last     = (const float*)d_in[2];
    const float* cache      = (const float*)d_in[3];
    const int*   block_ids  = (const int*)d_in[4];
    const int*   start_pos  = (const int*)d_in[5];
    const float* sink       = (const float*)d_in[6];
    float*       out        = (float*)d_out;

    dim3 grid(B_, HK_, NSPLIT);
    attn_fused_kernel<<<grid, NTHREADS>>>(q_last, k_last, v_last, cache,
                                          block_ids, start_pos, sink, out);
}

// round 5
// speedup vs baseline: 1.8200x; 1.0200x over previous
#include <cuda_runtime.h>
#include <math.h>

// Problem constants (fixed by the reference)
#define B_      8
#define HQ_     32
#define HK_     8
#define D_      64
#define S_      32
#define NB_     128
#define W_      1024
#define G_      (HQ_ / HK_)     // 4 q heads per kv head

#define NSPLIT  8
#define NWARPS  4
#define NTHREADS (NWARPS * 32)

// float4-unit strides in the cache [P, 2, Hk, S, D]:
#define PG4   8192      // 2*HK*S*D/4
#define HK4   512       // S*D/4
#define VP4   4096      // HK*S*D/4

// Split-KV scratch (no cudaMalloc allowed)
__device__ float g_l[B_ * HQ_ * NSPLIT];
__device__ float g_acc[B_ * HQ_ * NSPLIT * D_];
__device__ int   g_cnt[B_ * HK_];                 // zero-init; self-resetting

__device__ __forceinline__ float dot8(float4 qa, float4 qb, float4 ka, float4 kb)
{
    return qa.x*ka.x + qa.y*ka.y + qa.z*ka.z + qa.w*ka.w
         + qb.x*kb.x + qb.y*kb.y + qb.z*kb.z + qb.w*kb.w;
}

__global__ __launch_bounds__(NTHREADS)
void attn_fused_kernel(const float* __restrict__ q_last,
                       const float* __restrict__ k_last,
                       const float* __restrict__ v_last,
                       const float* __restrict__ cache,
                       const int*   __restrict__ block_ids,
                       const int*   __restrict__ start_pos,
                       const float* __restrict__ sink,
                       float*       __restrict__ out)
{
    const int b     = blockIdx.x;
    const int hk    = blockIdx.y;
    const int split = blockIdx.z;
    const int tid   = threadIdx.x;
    const int w     = tid >> 5;
    const int lane  = tid & 31;
    const int e     = lane & 7;        // 8 lanes cover a D=64 row (2x float4)
    const int q4    = lane >> 3;       // quad id within warp

    const int pos = start_pos[b];
    const int t0  = max(0, pos - W_ + 1);
    const int L   = pos - t0 + 1;
    const int chunk = (L + NSPLIT - 1) / NSPLIT;
    const int ts  = t0 + split * chunk;
    const int te  = min(ts + chunk, pos + 1);
    const int te2 = min(te, pos);      // main loop excludes t == pos

    const float4* cache4 = (const float4*)cache;
    const int*    bid    = block_ids + b * NB_;

    // q, pre-scaled by 1/sqrt(64): lane e holds float4 slices e and e+8
    float4 qa[G_], qb[G_];
#pragma unroll
    for (int g = 0; g < G_; g++) {
        const float4* qr = (const float4*)(q_last + ((size_t)(b * HQ_ + hk * G_ + g)) * D_);
        float4 a = qr[e], bb = qr[e + 8];
        qa[g] = make_float4(a.x*0.125f,  a.y*0.125f,  a.z*0.125f,  a.w*0.125f);
        qb[g] = make_float4(bb.x*0.125f, bb.y*0.125f, bb.z*0.125f, bb.w*0.125f);
    }

    float  l[G_];
    float4 acca[G_], accb[G_];
#pragma unroll
    for (int g = 0; g < G_; g++) {
        l[g] = 0.f;
        acca[g] = make_float4(0.f,0.f,0.f,0.f);
        accb[g] = make_float4(0.f,0.f,0.f,0.f);
    }

    const int khk = hk * HK4;

    // ---- main loop: 8 positions per warp-iteration, all loads front-batched ----
    for (int wb = ts + (w << 3); wb < te2; wb += NWARPS * 8) {
        const int tA = wb + q4;            // quad A positions
        const int tB = wb + 4 + q4;        // quad B positions
        const bool vA = tA < te2;
        const bool vB = tB < te2;
        const int tcA = vA ? tA : (te2 - 1);
        const int tcB = vB ? tB : (te2 - 1);
        const int iA = bid[tcA >> 5] * PG4 + khk + (tcA & 31) * 16 + e;
        const int iB = bid[tcB >> 5] * PG4 + khk + (tcB & 31) * 16 + e;

        // 8 independent LDG.128 per lane
        const float4 kaA = cache4[iA],       kbA = cache4[iA + 8];
        const float4 vaA = cache4[iA + VP4], vbA = cache4[iA + VP4 + 8];
        const float4 kaB = cache4[iB],       kbB = cache4[iB + 8];
        const float4 vaB = cache4[iB + VP4], vbB = cache4[iB + VP4 + 8];

        float sA[G_], sB[G_];
#pragma unroll
        for (int g = 0; g < G_; g++) {
            sA[g] = dot8(qa[g], qb[g], kaA, kbA);
            sB[g] = dot8(qa[g], qb[g], kaB, kbB);
        }
#pragma unroll
        for (int off = 4; off >= 1; off >>= 1) {
#pragma unroll
            for (int g = 0; g < G_; g++) {
                sA[g] += __shfl_xor_sync(0xffffffffu, sA[g], off);
                sB[g] += __shfl_xor_sync(0xffffffffu, sB[g], off);
            }
        }
#pragma unroll
        for (int g = 0; g < G_; g++) {
            const float pA = vA ? __expf(sA[g]) : 0.f;
            const float pB = vB ? __expf(sB[g]) : 0.f;
            l[g] += pA + pB;
            acca[g].x += pA * vaA.x + pB * vaB.x;
            acca[g].y += pA * vaA.y + pB * vaB.y;
            acca[g].z += pA * vaA.z + pB * vaB.z;
            acca[g].w += pA * vaA.w + pB * vaB.w;
            accb[g].x += pA * vbA.x + pB * vbB.x;
            accb[g].y += pA * vbA.y + pB * vbB.y;
            accb[g].z += pA * vbA.z + pB * vbB.z;
            accb[g].w += pA * vbA.w + pB * vbB.w;
        }
    }

    // ---- t == pos handled once, by warp 0 / lane-group 0 of the owning split ----
    if (pos >= ts && pos < te && w == 0 && lane < 8) {
        const float4* kr = (const float4*)(k_last + ((size_t)(b * HK_ + hk)) * D_);
        const float4* vr = (const float4*)(v_last + ((size_t)(b * HK_ + hk)) * D_);
        const float4 ka = kr[e], kb = kr[e + 8];
        const float4 va = vr[e], vb = vr[e + 8];
        float s[G_];
#pragma unroll
        for (int g = 0; g < G_; g++) s[g] = dot8(qa[g], qb[g], ka, kb);
#pragma unroll
        for (int off = 4; off >= 1; off >>= 1) {
#pragma unroll
            for (int g = 0; g < G_; g++)
                s[g] += __shfl_xor_sync(0x000000ffu, s[g], off);
        }
#pragma unroll
        for (int g = 0; g < G_; g++) {
            const float p = __expf(s[g]);
            l[g] += p;
            acca[g].x += p * va.x; acca[g].y += p * va.y;
            acca[g].z += p * va.z; acca[g].w += p * va.w;
            accb[g].x += p * vb.x; accb[g].y += p * vb.y;
            accb[g].z += p * vb.z; accb[g].w += p * vb.w;
        }
    }

    // ---- merge the 4 lane-groups of each warp (pure sums, no max) ----
#pragma unroll
    for (int g = 0; g < G_; g++) {
#pragma unroll
        for (int off = 8; off <= 16; off <<= 1) {
            l[g]      += __shfl_xor_sync(0xffffffffu, l[g], off);
            acca[g].x += __shfl_xor_sync(0xffffffffu, acca[g].x, off);
            acca[g].y += __shfl_xor_sync(0xffffffffu, acca[g].y, off);
            acca[g].z += __shfl_xor_sync(0xffffffffu, acca[g].z, off);
            acca[g].w += __shfl_xor_sync(0xffffffffu, acca[g].w, off);
            accb[g].x += __shfl_xor_sync(0xffffffffu, accb[g].x, off);
            accb[g].y += __shfl_xor_sync(0xffffffffu, accb[g].y, off);
            accb[g].z += __shfl_xor_sync(0xffffffffu, accb[g].z, off);
            accb[g].w += __shfl_xor_sync(0xffffffffu, accb[g].w, off);
        }
    }

    // ---- cross-warp combine via smem ----
    __shared__ float sl_[NWARPS][G_];
    __shared__ float sa_[NWARPS][G_][D_];
    if (lane < 8) {
#pragma unroll
        for (int g = 0; g < G_; g++) {
            ((float4*)sa_[w][g])[e]     = acca[g];
            ((float4*)sa_[w][g])[e + 8] = accb[g];
        }
    }
    if (lane == 0) {
#pragma unroll
        for (int g = 0; g < G_; g++) sl_[w][g] = l[g];
    }
    __syncthreads();

#pragma unroll
    for (int rep = 0; rep < 2; rep++) {
        const int i = tid + rep * NTHREADS;        // 0..255 -> (g,d)
        const int g = i >> 6;
        const int d = i & 63;
        float Lt = 0.f, A = 0.f;
#pragma unroll
        for (int ww = 0; ww < NWARPS; ww++) {
            Lt += sl_[ww][g];
            A  += sa_[ww][g][d];
        }
        const int idx = ((b * HK_ + hk) * G_ + g) * NSPLIT + split;
        if (d == 0) g_l[idx] = Lt;
        g_acc[idx * D_ + d] = A;
    }

    // ---- split-KV finalization: last CTA per (b,hk) reduces ----
    __shared__ int is_last;
    __threadfence();
    __syncthreads();
    if (tid == 0) {
        const int old = atomicAdd(&g_cnt[b * HK_ + hk], 1);
        is_last = (old == NSPLIT - 1);
    }
    __syncthreads();
    if (!is_last) return;
    __threadfence();

#pragma unroll
    for (int rep = 0; rep < 2; rep++) {
        const int i = tid + rep * NTHREADS;
        const int g = i >> 6;
        const int d = i & 63;
        const int hq = hk * G_ + g;
        const int base = ((b * HK_ + hk) * G_ + g) * NSPLIT;

        float Lt = __expf(sink[hq]);               // sink mass, denominator only
        float A  = 0.f;
#pragma unroll
        for (int s = 0; s < NSPLIT; s++) {
            Lt += g_l[base + s];
            A  += g_acc[(base + s) * D_ + d];
        }
        out[((size_t)(b * HQ_ + hq)) * D_ + d] = A / Lt;
    }
    if (tid == 0) g_cnt[b * HK_ + hk] = 0;         // reset for next graph replay
}

extern "C" void kernel_launch(void* const* d_in, const int* in_sizes, int n_in,
                              void* d_out, int out_size)
{
    const float* q_last     = (const float*)d_in[0];
    const float* k_last     = (const float*)d_in[1];
    const float* v_last     = (const float*)d_in[2];
    const float* cache      = (const float*)d_in[3];
    const int*   block_ids  = (const int*)d_in[4];
    const int*   start_pos  = (const int*)d_in[5];
    const float* sink       = (const float*)d_in[6];
    float*       out        = (float*)d_out;

    dim3 grid(B_, HK_, NSPLIT);
    attn_fused_kernel<<<grid, NTHREADS>>>(q_last, k_last, v_last, cache,
                                          block_ids, start_pos, sink, out);
}